// round 6
// baseline (speedup 1.0000x reference)
#include <cuda_runtime.h>
#include <cuda_fp16.h>
#include <cuda_pipeline.h>
#include <mma.h>
#include <cstdint>

using namespace nvcuda;

// Problem constants
#define BATCH   512
#define IN_DIM  256
#define OUT_DIM 256
#define NROWS   68          // G + K
#define KDENSE  80          // dense K per channel (68 padded to 80 = 5 x 16)
#define CG      16          // channels per block
#define MT      128         // M tile (batch)
#define NTILE   128         // N tile (outputs)
#define ZSPLIT  (IN_DIM / CG)   // 16
#define NTHREADS 256

// fp16 W copy: [k, c, n] layout, as 16B chunks (8 halfs). 8.9 MB.
#define WH_CHUNKS (NROWS * IN_DIM * OUT_DIM / 8)
__device__ uint4 g_wh[WH_CHUNKS];
// partial outputs: [z][b][n] fp32, 8 MB
__device__ float g_scratch[ZSPLIT * BATCH * OUT_DIM];

// smem layout (halfs padded for conflict-free LDSM)
#define A_STRIDE 88                         // 176B rows -> 8-row groups hit distinct banks
#define B_STRIDE 136                        // 272B rows -> distinct banks
#define A_BYTES  (MT * A_STRIDE * 2)        // 22528
#define B_BYTES  (KDENSE * B_STRIDE * 2)    // 21760
#define SMEM_TOTAL (2 * A_BYTES + 2 * B_BYTES)  // 88576 (stage reuses this region)

// ---------------- convert w to fp16 ----------------
__global__ void __launch_bounds__(256, 1)
convert_w_kernel(const float* __restrict__ w)
{
    int base = blockIdx.x * 256 + threadIdx.x;
    const int stride = gridDim.x * 256;
#pragma unroll 4
    for (int u = 0; u < 4; u++) {
        int i = base + u * stride;
        if (i < WH_CHUNKS) {
            const float4* src = (const float4*)w + i * 2;
            float4 a = src[0];
            float4 b = src[1];
            __half2 h0 = __floats2half2_rn(a.x, a.y);
            __half2 h1 = __floats2half2_rn(a.z, a.w);
            __half2 h2 = __floats2half2_rn(b.x, b.y);
            __half2 h3 = __floats2half2_rn(b.z, b.w);
            uint4 o;
            o.x = *(unsigned*)&h0; o.y = *(unsigned*)&h1;
            o.z = *(unsigned*)&h2; o.w = *(unsigned*)&h3;
            g_wh[i] = o;
        }
    }
}

// ---------------- basis + silu into A image ----------------
// t = [-1,-1,-1, linspace(-1,1,65), 1,1,1]; interior knots exact multiples of 2^-5.
__device__ __forceinline__ void gen_A(__half* arow, float xv, int* prevj)
{
    if (*prevj >= 0) {
        int pj = *prevj;
#pragma unroll
        for (int d = 0; d < 4; d++) arow[pj + d] = __ushort_as_half(0);
    }
    float f = (xv + 1.0f) * 32.0f;
    int j = (int)floorf(f);
    j = min(max(j, 0), 63);
    float tj  = -1.0f + (float)j * 0.03125f;
    float tj1 = -1.0f + (float)(j + 1) * 0.03125f;
    if (xv < tj) j--; else if (xv >= tj1) j++;
    j = min(max(j, 0), 63);

    float kn[6];
#pragma unroll
    for (int d = 0; d < 6; d++)
        kn[d] = -1.0f + (float)min(max(j + d - 2, 0), 64) * 0.03125f;

    float L1 = xv - kn[2], L2 = xv - kn[1], L3 = xv - kn[0];
    float R1 = kn[3] - xv, R2 = kn[4] - xv, R3 = kn[5] - xv;

    float temp, saved;
    temp = 1.0f / (R1 + L1);
    float n0 = R1 * temp;
    float n1 = L1 * temp;
    temp = n0 / (R1 + L2);
    float m0 = R1 * temp;  saved = L2 * temp;
    temp = n1 / (R2 + L1);
    float m1 = saved + R2 * temp;  float m2 = L1 * temp;
    temp = m0 / (R1 + L3);
    float q0 = R1 * temp;  saved = L3 * temp;
    temp = m1 / (R2 + L2);
    float q1 = saved + R2 * temp;  saved = L2 * temp;
    temp = m2 / (R3 + L1);
    float q2 = saved + R3 * temp;  float q3 = L1 * temp;

    float silu = xv / (1.0f + __expf(-xv));

    arow[j + 0] = __float2half_rn(q0);
    arow[j + 1] = __float2half_rn(q1);
    arow[j + 2] = __float2half_rn(q2);
    arow[j + 3] = __float2half_rn(q3);
    arow[67]    = __float2half_rn(silu);
    *prevj = j;
}

// ---------------- main WMMA kernel ----------------
__global__ void __launch_bounds__(NTHREADS, 1)
kan_wmma_kernel(const float* __restrict__ x)
{
    extern __shared__ __align__(256) char smem[];
    __half* A[2] = { (__half*)smem, (__half*)(smem + A_BYTES) };
    __half* B[2] = { (__half*)(smem + 2 * A_BYTES), (__half*)(smem + 2 * A_BYTES + B_BYTES) };

    const int tid = threadIdx.x;
    const int wid = tid >> 5;
    const int wm  = wid & 3;            // warp m: 0..3 (rows wm*32)
    const int wn  = wid >> 2;           // warp n: 0..1 (cols wn*64)
    const int b0  = blockIdx.x * MT;
    const int n0  = blockIdx.y * NTILE;
    const int c0  = blockIdx.z * CG;

    // zero all smem (A padding + B pad rows/cols stay zero forever)
    {
        uint4 z = make_uint4(0, 0, 0, 0);
        uint4* p = (uint4*)smem;
        for (int j = tid; j < SMEM_TOTAL / 16; j += NTHREADS) p[j] = z;
    }
    __syncthreads();

    const bool is_gen = (tid < 128);
    const int  m = tid;
    int prevj[2] = { -1, -1 };
    float x_cur = 0.f, x_next = 0.f;
    if (is_gen) {
        x_cur  = __ldg(x + (size_t)(b0 + m) * IN_DIM + c0);
        x_next = __ldg(x + (size_t)(b0 + m) * IN_DIM + c0 + 1);
    }

    // prologue: produce channel 0 into buffer 0
    if (is_gen) {
        gen_A(A[0] + m * A_STRIDE, x_cur, &prevj[0]);
        x_cur = x_next;
    } else {
        const int c = c0;
        uint4* dst = (uint4*)B[0];
        for (int j = tid - 128; j < NROWS * 16; j += 128) {
            int k = j >> 4, q = j & 15;
            __pipeline_memcpy_async(dst + k * 17 + q,
                g_wh + ((size_t)(k * IN_DIM + c) * 32) + blockIdx.y * 16 + q, 16);
        }
        __pipeline_commit();
    }

    wmma::fragment<wmma::accumulator, 16, 16, 16, float> acc[2][4];
#pragma unroll
    for (int i = 0; i < 2; i++)
#pragma unroll
        for (int j = 0; j < 4; j++) wmma::fill_fragment(acc[i][j], 0.0f);

    for (int c = 0; c < CG; c++) {
        const int cur = c & 1;
        if (c + 1 < CG) {
            const int nb = (c + 1) & 1;
            if (is_gen) {
                gen_A(A[nb] + m * A_STRIDE, x_cur, &prevj[nb]);
                if (c + 2 < CG)
                    x_cur = __ldg(x + (size_t)(b0 + m) * IN_DIM + c0 + c + 2);
            } else {
                const int ch = c0 + c + 1;
                uint4* dst = (uint4*)B[nb];
                for (int j = tid - 128; j < NROWS * 16; j += 128) {
                    int k = j >> 4, q = j & 15;
                    __pipeline_memcpy_async(dst + k * 17 + q,
                        g_wh + ((size_t)(k * IN_DIM + ch) * 32) + blockIdx.y * 16 + q, 16);
                }
                __pipeline_commit();
                __pipeline_wait_prior(1);   // channel c's B complete
            }
        } else if (!is_gen) {
            __pipeline_wait_prior(0);
        }
        __syncthreads();   // A(c), B(c) visible to all

        const __half* Ab = A[cur];
        const __half* Bb = B[cur];
#pragma unroll
        for (int kk = 0; kk < KDENSE / 16; kk++) {
            wmma::fragment<wmma::matrix_a, 16, 16, 16, __half, wmma::row_major> af[2];
            wmma::fragment<wmma::matrix_b, 16, 16, 16, __half, wmma::row_major> bf[4];
#pragma unroll
            for (int i = 0; i < 2; i++)
                wmma::load_matrix_sync(af[i],
                    Ab + (wm * 32 + i * 16) * A_STRIDE + kk * 16, A_STRIDE);
#pragma unroll
            for (int j = 0; j < 4; j++)
                wmma::load_matrix_sync(bf[j],
                    Bb + (kk * 16) * B_STRIDE + wn * 64 + j * 16, B_STRIDE);
#pragma unroll
            for (int i = 0; i < 2; i++)
#pragma unroll
                for (int j = 0; j < 4; j++)
                    wmma::mma_sync(acc[i][j], af[i], bf[j], acc[i][j]);
        }
        __syncthreads();   // mma(c) done before buffers are overwritten
    }

    // epilogue: stage fp32 tile in smem (reuses A/B region), then STG to scratch
    float* stage = (float*)smem;
#pragma unroll
    for (int i = 0; i < 2; i++)
#pragma unroll
        for (int j = 0; j < 4; j++)
            wmma::store_matrix_sync(
                stage + (wm * 32 + i * 16) * NTILE + wn * 64 + j * 16,
                acc[i][j], NTILE, wmma::mem_row_major);
    __syncthreads();

    {
        float* dstb = g_scratch + ((size_t)blockIdx.z * BATCH + b0) * OUT_DIM + n0;
        const float4* st4 = (const float4*)stage;
#pragma unroll
        for (int r = 0; r < 16; r++) {
            int q  = r * NTHREADS + tid;      // float4 index in 128x128 tile
            int mm = q >> 5;
            int nn = q & 31;
            ((float4*)(dstb + (size_t)mm * OUT_DIM))[nn] = st4[q];
        }
    }
}

// ---------------- reduce partials ----------------
__global__ void __launch_bounds__(256, 1)
reduce_kernel(float4* __restrict__ out)
{
    int i = blockIdx.x * 256 + threadIdx.x;    // float4 index over 32768
    const float4* s = (const float4*)g_scratch;
    float4 a = s[i];
#pragma unroll
    for (int z = 1; z < ZSPLIT; z++) {
        float4 b = s[(size_t)z * (BATCH * OUT_DIM / 4) + i];
        a.x += b.x; a.y += b.y; a.z += b.z; a.w += b.w;
    }
    out[i] = a;
}

extern "C" void kernel_launch(void* const* d_in, const int* in_sizes, int n_in,
                              void* d_out, int out_size)
{
    const float* x = (const float*)d_in[0];
    const float* w = (const float*)d_in[1];
    float* out = (float*)d_out;

    cudaFuncSetAttribute(kan_wmma_kernel,
                         cudaFuncAttributeMaxDynamicSharedMemorySize, SMEM_TOTAL);

    convert_w_kernel<<<(WH_CHUNKS + 1023) / 1024, 256>>>(w);

    dim3 grid(BATCH / MT, OUT_DIM / NTILE, ZSPLIT);
    kan_wmma_kernel<<<grid, NTHREADS, SMEM_TOTAL>>>(x);

    reduce_kernel<<<(BATCH * OUT_DIM / 4) / 256, 256>>>((float4*)out);
}

// round 7
// speedup vs baseline: 1.0525x; 1.0525x over previous
#include <cuda_runtime.h>
#include <cuda_fp16.h>
#include <cuda_pipeline.h>
#include <mma.h>
#include <cstdint>

using namespace nvcuda;

// Problem constants
#define BATCH   512
#define IN_DIM  256
#define OUT_DIM 256
#define NROWS   68          // G + K
#define KDENSE  80          // dense K per channel (68 padded to 80 = 5 x 16)
#define CG      16          // channels per block
#define MT      128         // M tile (batch)
#define NTILE   128         // N tile (outputs)
#define ZSPLIT  (IN_DIM / CG)   // 16
#define NTHREADS 256

// fp16 W copy: [k, c, n] layout, as 16B chunks (8 halfs). 8.9 MB.
#define WH_CHUNKS (NROWS * IN_DIM * OUT_DIM / 8)   // 557056
__device__ uint4 g_wh[WH_CHUNKS];
// partial outputs: [z][b][n] fp32, 8 MB
__device__ float g_scratch[ZSPLIT * BATCH * OUT_DIM];

// smem layout (halfs padded for conflict-free LDSM), TRIPLE buffered
#define A_STRIDE 88                         // 176B rows
#define B_STRIDE 136                        // 272B rows (17 uint4)
#define A_BYTES  (MT * A_STRIDE * 2)        // 22528
#define B_BYTES  (KDENSE * B_STRIDE * 2)    // 21760
#define SMEM_TOTAL (3 * A_BYTES + 3 * B_BYTES)  // 132864; epilogue stage reuses A region

// ---------------- convert w to fp16 (high-MLP) ----------------
// 544 blocks x 256 threads x 4 chunks each = 557056 chunks exactly.
__global__ void __launch_bounds__(256, 4)
convert_w_kernel(const float* __restrict__ w)
{
    const int i0 = blockIdx.x * 1024 + threadIdx.x;
    const float4* src = (const float4*)w;

    float4 v[8];
#pragma unroll
    for (int u = 0; u < 4; u++) {
        int i = i0 + u * 256;
        v[2 * u]     = src[(size_t)i * 2];
        v[2 * u + 1] = src[(size_t)i * 2 + 1];
    }
#pragma unroll
    for (int u = 0; u < 4; u++) {
        __half2 h0 = __floats2half2_rn(v[2 * u].x,     v[2 * u].y);
        __half2 h1 = __floats2half2_rn(v[2 * u].z,     v[2 * u].w);
        __half2 h2 = __floats2half2_rn(v[2 * u + 1].x, v[2 * u + 1].y);
        __half2 h3 = __floats2half2_rn(v[2 * u + 1].z, v[2 * u + 1].w);
        uint4 o;
        o.x = *(unsigned*)&h0; o.y = *(unsigned*)&h1;
        o.z = *(unsigned*)&h2; o.w = *(unsigned*)&h3;
        g_wh[i0 + u * 256] = o;
    }
}

// ---------------- basis + silu into A image ----------------
// t = [-1,-1,-1, linspace(-1,1,65), 1,1,1]; interior knots exact multiples of 2^-5.
__device__ __forceinline__ void gen_A(__half* arow, float xv, int* prevj)
{
    if (*prevj >= 0) {
        int pj = *prevj;
#pragma unroll
        for (int d = 0; d < 4; d++) arow[pj + d] = __ushort_as_half(0);
    }
    float f = (xv + 1.0f) * 32.0f;
    int j = (int)floorf(f);
    j = min(max(j, 0), 63);
    float tj  = -1.0f + (float)j * 0.03125f;
    float tj1 = -1.0f + (float)(j + 1) * 0.03125f;
    if (xv < tj) j--; else if (xv >= tj1) j++;
    j = min(max(j, 0), 63);

    float kn[6];
#pragma unroll
    for (int d = 0; d < 6; d++)
        kn[d] = -1.0f + (float)min(max(j + d - 2, 0), 64) * 0.03125f;

    float L1 = xv - kn[2], L2 = xv - kn[1], L3 = xv - kn[0];
    float R1 = kn[3] - xv, R2 = kn[4] - xv, R3 = kn[5] - xv;

    float temp, saved;
    temp = 1.0f / (R1 + L1);
    float n0 = R1 * temp;
    float n1 = L1 * temp;
    temp = n0 / (R1 + L2);
    float m0 = R1 * temp;  saved = L2 * temp;
    temp = n1 / (R2 + L1);
    float m1 = saved + R2 * temp;  float m2 = L1 * temp;
    temp = m0 / (R1 + L3);
    float q0 = R1 * temp;  saved = L3 * temp;
    temp = m1 / (R2 + L2);
    float q1 = saved + R2 * temp;  saved = L2 * temp;
    temp = m2 / (R3 + L1);
    float q2 = saved + R3 * temp;  float q3 = L1 * temp;

    float silu = xv / (1.0f + __expf(-xv));

    arow[j + 0] = __float2half_rn(q0);
    arow[j + 1] = __float2half_rn(q1);
    arow[j + 2] = __float2half_rn(q2);
    arow[j + 3] = __float2half_rn(q3);
    arow[67]    = __float2half_rn(silu);
    *prevj = j;
}

// ---------------- main WMMA kernel (triple-buffered, 1 barrier/channel) ----------------
__global__ void __launch_bounds__(NTHREADS, 1)
kan_wmma_kernel(const float* __restrict__ x)
{
    extern __shared__ __align__(256) char smem[];
    __half* A[3];
    __half* B[3];
#pragma unroll
    for (int i = 0; i < 3; i++) {
        A[i] = (__half*)(smem + i * A_BYTES);
        B[i] = (__half*)(smem + 3 * A_BYTES + i * B_BYTES);
    }

    const int tid = threadIdx.x;
    const int wid = tid >> 5;
    const int wm  = wid & 3;            // warp m: rows wm*32
    const int wn  = wid >> 2;           // warp n: cols wn*64
    const int b0  = blockIdx.x * MT;
    const int n0  = blockIdx.y * NTILE;
    const int c0  = blockIdx.z * CG;

    // zero all smem (A padding + B pad rows/cols stay zero forever)
    {
        uint4 z = make_uint4(0, 0, 0, 0);
        uint4* p = (uint4*)smem;
        for (int j = tid; j < SMEM_TOTAL / 16; j += NTHREADS) p[j] = z;
    }
    __syncthreads();

    const bool is_gen = (tid < 128);
    const int  m = tid;
    int prevj[3] = { -1, -1, -1 };
    float x_cur = 0.f, x_next = 0.f;
    if (is_gen) {
        x_cur  = __ldg(x + (size_t)(b0 + m) * IN_DIM + c0);
        x_next = __ldg(x + (size_t)(b0 + m) * IN_DIM + c0 + 1);
    }

    // prologue: produce channel 0 into buffer 0
    if (is_gen) {
        gen_A(A[0] + m * A_STRIDE, x_cur, &prevj[0]);
        x_cur = x_next;
    } else {
        const int c = c0;
        uint4* dst = (uint4*)B[0];
        for (int j = tid - 128; j < NROWS * 16; j += 128) {
            int k = j >> 4, q = j & 15;
            __pipeline_memcpy_async(dst + k * 17 + q,
                g_wh + ((size_t)(k * IN_DIM + c) * 32) + blockIdx.y * 16 + q, 16);
        }
        __pipeline_commit();
    }

    wmma::fragment<wmma::accumulator, 16, 16, 16, float> acc[2][4];
#pragma unroll
    for (int i = 0; i < 2; i++)
#pragma unroll
        for (int j = 0; j < 4; j++) wmma::fill_fragment(acc[i][j], 0.0f);

    for (int c = 0; c < CG; c++) {
        // produce channel c+1 into buffer (c+1)%3
        if (c + 1 < CG) {
            const int nb = (c + 1) % 3;
            if (is_gen) {
                gen_A(A[nb] + m * A_STRIDE, x_cur, &prevj[nb]);
                if (c + 2 < CG)
                    x_cur = __ldg(x + (size_t)(b0 + m) * IN_DIM + c0 + c + 2);
            } else {
                const int ch = c0 + c + 1;
                uint4* dst = (uint4*)B[nb];
                for (int j = tid - 128; j < NROWS * 16; j += 128) {
                    int k = j >> 4, q = j & 15;
                    __pipeline_memcpy_async(dst + k * 17 + q,
                        g_wh + ((size_t)(k * IN_DIM + ch) * 32) + blockIdx.y * 16 + q, 16);
                }
                __pipeline_commit();
                __pipeline_wait_prior(1);   // channel c's B complete
            }
        } else if (!is_gen) {
            __pipeline_wait_prior(0);
        }
        __syncthreads();   // single barrier per channel (triple buffering)

        const __half* Ab = A[c % 3];
        const __half* Bb = B[c % 3];
#pragma unroll
        for (int kk = 0; kk < KDENSE / 16; kk++) {
            wmma::fragment<wmma::matrix_a, 16, 16, 16, __half, wmma::row_major> af[2];
            wmma::fragment<wmma::matrix_b, 16, 16, 16, __half, wmma::row_major> bf[4];
#pragma unroll
            for (int i = 0; i < 2; i++)
                wmma::load_matrix_sync(af[i],
                    Ab + (wm * 32 + i * 16) * A_STRIDE + kk * 16, A_STRIDE);
#pragma unroll
            for (int j = 0; j < 4; j++)
                wmma::load_matrix_sync(bf[j],
                    Bb + (kk * 16) * B_STRIDE + wn * 64 + j * 16, B_STRIDE);
#pragma unroll
            for (int i = 0; i < 2; i++)
#pragma unroll
                for (int j = 0; j < 4; j++)
                    wmma::mma_sync(acc[i][j], af[i], bf[j], acc[i][j]);
        }
    }
    __syncthreads();   // all MMAs done before smem is reused as epilogue stage

    // epilogue: stage fp32 tile in smem (reuses A region), then STG to scratch
    float* stage = (float*)smem;
#pragma unroll
    for (int i = 0; i < 2; i++)
#pragma unroll
        for (int j = 0; j < 4; j++)
            wmma::store_matrix_sync(
                stage + (wm * 32 + i * 16) * NTILE + wn * 64 + j * 16,
                acc[i][j], NTILE, wmma::mem_row_major);
    __syncthreads();

    {
        float* dstb = g_scratch + ((size_t)blockIdx.z * BATCH + b0) * OUT_DIM + n0;
        const float4* st4 = (const float4*)stage;
#pragma unroll
        for (int r = 0; r < 16; r++) {
            int q  = r * NTHREADS + tid;      // float4 index in 128x128 tile
            int mm = q >> 5;
            int nn = q & 31;
            ((float4*)(dstb + (size_t)mm * OUT_DIM))[nn] = st4[q];
        }
    }
}

// ---------------- reduce partials ----------------
__global__ void __launch_bounds__(256, 1)
reduce_kernel(float4* __restrict__ out)
{
    int i = blockIdx.x * 256 + threadIdx.x;    // float4 index over 32768
    const float4* s = (const float4*)g_scratch;
    float4 a = s[i];
#pragma unroll
    for (int z = 1; z < ZSPLIT; z++) {
        float4 b = s[(size_t)z * (BATCH * OUT_DIM / 4) + i];
        a.x += b.x; a.y += b.y; a.z += b.z; a.w += b.w;
    }
    out[i] = a;
}

extern "C" void kernel_launch(void* const* d_in, const int* in_sizes, int n_in,
                              void* d_out, int out_size)
{
    const float* x = (const float*)d_in[0];
    const float* w = (const float*)d_in[1];
    float* out = (float*)d_out;

    cudaFuncSetAttribute(kan_wmma_kernel,
                         cudaFuncAttributeMaxDynamicSharedMemorySize, SMEM_TOTAL);

    convert_w_kernel<<<WH_CHUNKS / 1024, 256>>>(w);

    dim3 grid(BATCH / MT, OUT_DIM / NTILE, ZSPLIT);
    kan_wmma_kernel<<<grid, NTHREADS, SMEM_TOTAL>>>(x);

    reduce_kernel<<<(BATCH * OUT_DIM / 4) / 256, 256>>>((float4*)out);
}